// round 15
// baseline (speedup 1.0000x reference)
#include <cuda_runtime.h>
#include <cuda_bf16.h>
#include <cstdint>

#define N_ATOMS   5000
#define N_EDGES   200000
#define N_TRIPLES 4000000
#define D_NODE    128
#define D_EDGE    128
#define N_BASIS   9

// Scratch (no allocations allowed)
__device__ float g_atoms[N_ATOMS * N_BASIS];       // sigmoid(node@W_atom+b) [5000 x 9]
__device__ float g_edge_atoms[N_EDGES * N_BASIS];  // atoms[graph_dst[e]]    [200000 x 9]
__device__ float g_new_bonds[N_EDGES * N_BASIS];   // segment sums           [200000 x 9]
__device__ int   g_seg_start[N_EDGES + 1];         // run boundaries in sorted seg_ids

// packed f32x2 helpers (Blackwell FFMA2 is only reachable via PTX)
#define FMA2(d, a, b, c) \
    asm("fma.rn.f32x2 %0, %1, %2, %3;" : "=l"(d) : "l"(a), "l"(b), "l"(c))
#define PACK2(out, lo, hi) \
    asm("mov.b64 %0, {%1, %2};" : "=l"(out) : "f"(lo), "f"(hi))
#define UNPACK2(lo, hi, in) \
    asm("mov.b64 {%0, %1}, %2;" : "=f"(lo), "=f"(hi) : "l"(in))

// ---------------------------------------------------------------------------
// Kernel 1 (FUSED): blocks [0, ATOM_BLOCKS) compute the atoms table;
// blocks [ATOM_BLOCKS, ..) compute seg_start via binary search.
// ---------------------------------------------------------------------------
#define PREP_TPB     256
#define ATOM_BLOCKS  ((N_ATOMS * N_BASIS + PREP_TPB - 1) / PREP_TPB)      // 176
#define SEG_BLOCKS   ((N_EDGES + 1 + PREP_TPB - 1) / PREP_TPB)            // 782
#define PREP_GRID    (ATOM_BLOCKS + SEG_BLOCKS)

__global__ void prep_kernel(const float* __restrict__ node_feat,
                            const float* __restrict__ W_atom,
                            const float* __restrict__ b_atom,
                            const int*   __restrict__ seg_ids) {
    if (blockIdx.x < ATOM_BLOCKS) {
        int id = blockIdx.x * PREP_TPB + threadIdx.x;
        if (id >= N_ATOMS * N_BASIS) return;
        int a = id / N_BASIS;
        int j = id % N_BASIS;
        float acc = b_atom[j];
        const float* nf = node_feat + a * D_NODE;
        #pragma unroll 8
        for (int k = 0; k < D_NODE; k++)
            acc = fmaf(nf[k], W_atom[k * N_BASIS + j], acc);
        g_atoms[id] = 1.0f / (1.0f + __expf(-acc));
    } else {
        int e = (blockIdx.x - ATOM_BLOCKS) * PREP_TPB + threadIdx.x;
        if (e > N_EDGES) return;
        if (e == N_EDGES) { g_seg_start[N_EDGES] = N_TRIPLES; return; }
        int lo = 0, hi = N_TRIPLES;
        while (lo < hi) {
            int mid = (lo + hi) >> 1;
            if (__ldg(seg_ids + mid) < e) lo = mid + 1; else hi = mid;
        }
        g_seg_start[e] = lo;
    }
}

// ---------------------------------------------------------------------------
// Kernel 1c: edge_atoms[e][j] = atoms[graph_dst[e]][j]   (7.2 MB, L2-resident)
// ---------------------------------------------------------------------------
__global__ void edge_atoms_kernel(const int* __restrict__ graph_dst) {
    int id = blockIdx.x * blockDim.x + threadIdx.x;
    if (id >= N_EDGES * N_BASIS) return;
    int e2 = id / N_BASIS;
    int j  = id - e2 * N_BASIS;
    g_edge_atoms[id] = g_atoms[__ldg(graph_dst + e2) * N_BASIS + j];
}

// ---------------------------------------------------------------------------
// Kernel 2 (v11 + streaming hints): warp-per-edge, tiered batches.
// three_basis / lg_dst are read ONCE -> __ldcs (evict-first) keeps the
// L2-resident edge_atoms table (latency-critical gathers) from being
// thrashed by 160 MB of streaming traffic.
// ---------------------------------------------------------------------------
#define TPB_T    512
#define GRID_T   592                          // 4 blocks/SM x 148
#define NWARPS_T (GRID_T * (TPB_T / 32))      // 9472
#define UB4 4

__global__ __launch_bounds__(TPB_T, 4) void triples_kernel(
    const float* __restrict__ three_basis,
    const int*   __restrict__ lg_dst) {

    const int lane   = threadIdx.x & 31;
    const int group  = lane / 9;               // 0,1,2 (3 for lanes 27..31)
    const int j      = lane - group * 9;       // basis column
    const bool active = (lane < 27);
    const int warp_global = blockIdx.x * (TPB_T / 32) + (threadIdx.x >> 5);

    // per-thread pre-offset ea base: gather addr = eab + 36*lg
    const char* eab = (const char*)g_edge_atoms + 4 * j;

    for (int e = warp_global; e < N_EDGES; e += NWARPS_T) {
        const int s   = __ldg(g_seg_start + e);
        const int len = __ldg(g_seg_start + e + 1) - s;

        // clamp inactive lanes to offset 0: all unpredicated loads in-bounds
        const float* tbp = three_basis + (active ? (size_t)s * 9 + lane : 0);
        const int*   lgp = lg_dst + (active ? s + group : 0);

        float acc = 0.f;
        int k0 = 0;

        // tier 1: unpredicated batches of 4 steps (12 triples)
        for (; k0 + 12 <= len; k0 += 12) {
            float v[UB4];
            int   lgv[UB4];
            #pragma unroll
            for (int u = 0; u < UB4; u++) {
                v[u]   = __ldcs(tbp + 9 * (k0 + 3 * u));
                lgv[u] = __ldcs(lgp + k0 + 3 * u);
            }
            #pragma unroll
            for (int u = 0; u < UB4; u++)
                acc = fmaf(v[u],
                           __ldg((const float*)(eab + 36 * (size_t)lgv[u])),
                           acc);
        }
        // tier 2: unpredicated single steps (3 triples)
        for (; k0 + 3 <= len; k0 += 3) {
            float v  = __ldcs(tbp + 9 * k0);
            int  lgv = __ldcs(lgp + k0);
            acc = fmaf(v, __ldg((const float*)(eab + 36 * (size_t)lgv)), acc);
        }
        // tier 3: final partial step (len - k0 in {1,2})
        if (k0 < len) {
            const bool p = active && (k0 + group) < len;
            float v  = p ? __ldcs(tbp + 9 * k0) : 0.f;
            int  lgv = p ? __ldcs(lgp + k0)     : 0;
            acc = fmaf(v, __ldg((const float*)(eab + 36 * (size_t)lgv)), acc);
        }

        float a1 = __shfl_down_sync(0xFFFFFFFFu, acc, 9);
        float a2 = __shfl_down_sync(0xFFFFFFFFu, acc, 18);
        if (lane < N_BASIS)
            g_new_bonds[(size_t)e * N_BASIS + lane] = acc + a1 + a2;
    }
}

// ---------------------------------------------------------------------------
// Kernel 3: persistent grid-stride + f32x2 FMA.
// __launch_bounds__(128, 12): force regs <= 42 (was 48, which capped
// residency at 10 blocks/SM -> 51% occ). Streaming hints on the 205 MB
// edge_feat/out traffic (read/written exactly once).
// ---------------------------------------------------------------------------
#define E_TILE   64
#define NB_TILE  (E_TILE * N_BASIS)            // 576 floats
#define N_TILES  (N_EDGES / E_TILE)            // 3125
#define MLP_GRID 2368                          // 16 blocks/SM * 148

__global__ __launch_bounds__(D_EDGE, 12) void mlp_kernel(
    const float* __restrict__ edge_feat,
    const float* __restrict__ W_gate, const float* __restrict__ b_gate,
    const float* __restrict__ W_sig,  const float* __restrict__ b_sig,
    float* __restrict__ out) {

    __shared__ float s_nb[NB_TILE];            // transposed [9][E_TILE]

    const int j = threadIdx.x;

    uint64_t wg2[N_BASIS], ws2[N_BASIS], bg2, bs2;
    #pragma unroll
    for (int k = 0; k < N_BASIS; k++) {
        float wgk = W_gate[k * D_EDGE + j];
        float wsk = W_sig [k * D_EDGE + j];
        PACK2(wg2[k], wgk, wgk);
        PACK2(ws2[k], wsk, wsk);
    }
    {
        float bgv = b_gate[j], bsv = b_sig[j];
        PACK2(bg2, bgv, bgv);
        PACK2(bs2, bsv, bsv);
    }

    for (int tile = blockIdx.x; tile < N_TILES; tile += MLP_GRID) {
        const int e0 = tile * E_TILE;

        __syncthreads();
        const float* nb_src = g_new_bonds + (size_t)e0 * N_BASIS;
        #pragma unroll
        for (int i = j; i < NB_TILE; i += D_EDGE) {
            int ee = i / N_BASIS, kk = i - ee * N_BASIS;
            s_nb[kk * E_TILE + ee] = nb_src[i];    // transpose on store
        }
        __syncthreads();

        #pragma unroll 2
        for (int e = 0; e < E_TILE; e += 2) {
            size_t idx0 = (size_t)(e0 + e) * D_EDGE + j;
            size_t idx1 = idx0 + D_EDGE;
            float ef0 = __ldcs(edge_feat + idx0);   // streaming read
            float ef1 = __ldcs(edge_feat + idx1);

            uint64_t accg = bg2, accs = bs2;
            #pragma unroll
            for (int k = 0; k < N_BASIS; k++) {
                uint64_t n2 = *reinterpret_cast<const uint64_t*>(
                                  &s_nb[k * E_TILE + e]);   // LDS.64 broadcast
                FMA2(accg, n2, wg2[k], accg);
                FMA2(accs, n2, ws2[k], accs);
            }
            float g0, g1, s0, s1;
            UNPACK2(g0, g1, accg);
            UNPACK2(s0, s1, accs);

            // up = g / ((1+e^-g)(1+e^-s)) == silu(g)*sigmoid(s)
            float d0 = (1.f + __expf(-g0)) * (1.f + __expf(-s0));
            float d1 = (1.f + __expf(-g1)) * (1.f + __expf(-s1));
            __stcs(out + idx0, ef0 + __fdividef(g0, d0));   // streaming write
            __stcs(out + idx1, ef1 + __fdividef(g1, d1));
        }
    }
}

// ---------------------------------------------------------------------------
// Launch (4 kernels)
// ---------------------------------------------------------------------------
extern "C" void kernel_launch(void* const* d_in, const int* in_sizes, int n_in,
                              void* d_out, int out_size) {
    const float* node_feat   = (const float*)d_in[0];
    const float* edge_feat   = (const float*)d_in[1];
    const float* three_basis = (const float*)d_in[2];
    const float* W_atom      = (const float*)d_in[4];
    const float* b_atom      = (const float*)d_in[5];
    const float* W_gate      = (const float*)d_in[6];
    const float* b_gate      = (const float*)d_in[7];
    const float* W_sig       = (const float*)d_in[8];
    const float* b_sig       = (const float*)d_in[9];
    const int*   graph_dst   = (const int*)d_in[10];
    const int*   lg_dst      = (const int*)d_in[12];
    const int*   seg_ids     = (const int*)d_in[13];
    float*       out         = (float*)d_out;

    prep_kernel<<<PREP_GRID, PREP_TPB>>>(node_feat, W_atom, b_atom, seg_ids);
    edge_atoms_kernel<<<(N_EDGES * N_BASIS + 255) / 256, 256>>>(graph_dst);
    triples_kernel<<<GRID_T, TPB_T>>>(three_basis, lg_dst);
    mlp_kernel<<<MLP_GRID, D_EDGE>>>(edge_feat, W_gate, b_gate, W_sig, b_sig, out);
}